// round 17
// baseline (speedup 1.0000x reference)
#include <cuda_runtime.h>
#include <cuda_bf16.h>
#include <cuda_fp16.h>
#include <cstdint>

#define NTOT 65536
#define DDIM 512
#define KCL  64

#define BN 64               // d-columns per CTA tile
#define BK 32               // k rows per stage
#define DTILES 8            // DDIM / BN
#define NCHUNKS 55          // grid = 8*55 = 440 CTAs <= 444 = 3 CTAs/SM wave
#define NCTAS (DTILES * NCHUNKS)

#define SF_B 144            // F smem row stride bytes (64 f16 = 128 + 16 pad)
#define SH_B 144            // H smem row stride bytes (64 f16 = 128 + 16 pad)

__device__ float        g_partial[KCL * DDIM];  // .bss zero; re-zeroed per call
__device__ float        g_h2sum;
__device__ unsigned int g_count;

__device__ __forceinline__ uint32_t smem_u32(const void* p) {
    return (uint32_t)__cvta_generic_to_shared(p);
}

__device__ __forceinline__ uint32_t pack_f16(float lo, float hi) {
    uint32_t r;
    asm("cvt.rn.f16x2.f32 %0, %1, %2;" : "=r"(r) : "f"(hi), "f"(lo));
    return r;
}

__device__ __forceinline__ void ldsm4t(uint32_t* r, uint32_t addr) {
    asm volatile(
        "ldmatrix.sync.aligned.m8n8.x4.trans.shared.b16 {%0,%1,%2,%3}, [%4];"
        : "=r"(r[0]), "=r"(r[1]), "=r"(r[2]), "=r"(r[3]) : "r"(addr));
}

__global__ __launch_bounds__(256, 3)
void k_fused(const float* __restrict__ H, const float* __restrict__ Fm,
             float* __restrict__ out) {
    // smem tiles in gmem order: rows = k
    __shared__ __align__(16) char Fs[2][BK * SF_B];   // 2 x 4608 B
    __shared__ __align__(16) char Hs[2][BK * SH_B];   // 2 x 4608 B
    __shared__ float        redbuf[8];
    __shared__ double       sb[8];
    __shared__ unsigned int s_ticket;

    const int tid  = threadIdx.x;
    const int lane = tid & 31;
    const int wid  = tid >> 5;
    const int d0   = blockIdx.x * BN;
    const int c    = blockIdx.y;

    // 2048 k-blocks over 55 chunks: chunks 0..12 get 38, 13..54 get 37
    const int kb_start = c * 37 + (c < 13 ? c : 13);
    const int ITERS    = 37 + (c < 13 ? 1 : 0);
    const int nb0      = kb_start * BK;

    const int wm = (wid >> 1) * 16;     // 4 warp rows along m (16 each)
    const int wn = (wid & 1) * 32;      // 2 warp cols along n (32 each)
    const int g  = lane >> 2;
    const int t  = lane & 3;

    // producer mapping: thread -> rows (tid>>4) and (tid>>4)+16, quad tid&15
    const int pr = tid >> 4;            // 0..15
    const int pq = tid & 15;            // float4 index within row

    // LDSM per-lane offsets (bytes) — R9/R15-proven formulas
    const uint32_t a_lane = (uint32_t)(((lane >> 4) & 1) * (8 * SF_B)
                                       + (lane & 7) * SF_B
                                       + ((lane >> 3) & 1) * 16);
    const uint32_t b_lane = (uint32_t)(((lane >> 3) & 1) * (8 * SH_B)
                                       + (lane & 7) * SH_B
                                       + ((lane >> 4) & 1) * 16);

    uint32_t acc[4][2];                 // f16x2 accumulators (R15-proven)
#pragma unroll
    for (int a = 0; a < 4; a++) { acc[a][0] = 0u; acc[a][1] = 0u; }

    float h2 = 0.f;

    // distance-2 register staging: two slots
    float4 rf[2][2], rh[2][2];

    auto gload = [&](int it, int slot) {
        const int nb = nb0 + it * BK;
#pragma unroll
        for (int j = 0; j < 2; j++) {
            const int k = nb + pr + 16 * j;
            rf[slot][j] = *(const float4*)&Fm[(size_t)k * KCL + pq * 4];
            rh[slot][j] = *(const float4*)&H[(size_t)k * DDIM + d0 + pq * 4];
        }
    };

    auto sstore = [&](int buf, int slot) {
        char* fb = Fs[buf];
        char* hb = Hs[buf];
#pragma unroll
        for (int j = 0; j < 2; j++) {
            const int k = pr + 16 * j;
            float4 f4 = rf[slot][j];
            *(uint2*)(fb + k * SF_B + pq * 8) =
                make_uint2(pack_f16(f4.x, f4.y), pack_f16(f4.z, f4.w));
            float4 v = rh[slot][j];
            *(uint2*)(hb + k * SH_B + pq * 8) =
                make_uint2(pack_f16(v.x, v.y), pack_f16(v.z, v.w));
            h2 = fmaf(v.x, v.x, h2);
            h2 = fmaf(v.y, v.y, h2);
            h2 = fmaf(v.z, v.z, h2);
            h2 = fmaf(v.w, v.w, h2);
        }
    };

    auto compute = [&](int buf) {
        const uint32_t aBase = smem_u32(Fs[buf]) + (uint32_t)(wm * 2) + a_lane;
        const uint32_t bBase = smem_u32(Hs[buf]) + (uint32_t)(wn * 2) + b_lane;
#pragma unroll
        for (int ks = 0; ks < 2; ks++) {          // two k16 steps per BK=32
            uint32_t a[4], b[2][4];
            ldsm4t(a, aBase + ks * (16 * SF_B));
            ldsm4t(b[0], bBase + ks * (16 * SH_B));
            ldsm4t(b[1], bBase + ks * (16 * SH_B) + 32);      // n + 16
#pragma unroll
            for (int ni = 0; ni < 4; ni++) {
                const uint32_t b0 = b[ni >> 1][(ni & 1) * 2];
                const uint32_t b1 = b[ni >> 1][(ni & 1) * 2 + 1];
                asm volatile(
                    "mma.sync.aligned.m16n8k16.row.col.f16.f16.f16.f16 "
                    "{%0,%1}, {%2,%3,%4,%5}, {%6,%7}, {%0,%1};\n"
                    : "+r"(acc[ni][0]), "+r"(acc[ni][1])
                    : "r"(a[0]), "r"(a[1]), "r"(a[2]), "r"(a[3]),
                      "r"(b0), "r"(b1));
            }
        }
    };

    // ---- pipeline: double smem buffer, register prefetch DISTANCE 2 ----
    gload(0, 0);
    if (ITERS > 1) gload(1, 1);
    sstore(0, 0);
    __syncthreads();

#pragma unroll 1
    for (int it = 0; it < ITERS; ++it) {
        // slot it&1 was drained by sstore at iteration it-1 (program order)
        if (it + 2 < ITERS) gload(it + 2, it & 1);
        compute(it & 1);
        if (it + 1 < ITERS) sstore((it + 1) & 1, (it + 1) & 1);
        __syncthreads();
    }

    // ---- epilogue: unpack f16 acc, packed float2 L2 atomics ----
#pragma unroll
    for (int ni = 0; ni < 4; ni++) {
        int m = wm + g;
        int n = d0 + wn + ni * 8 + 2 * t;
        __half2 c0 = *reinterpret_cast<__half2*>(&acc[ni][0]);
        __half2 c1 = *reinterpret_cast<__half2*>(&acc[ni][1]);
        atomicAdd((float2*)&g_partial[m * DDIM + n],
                  make_float2(__low2float(c0), __high2float(c0)));
        atomicAdd((float2*)&g_partial[(m + 8) * DDIM + n],
                  make_float2(__low2float(c1), __high2float(c1)));
    }

    // ---- h2 block reduce, one atomic per CTA ----
#pragma unroll
    for (int o = 16; o > 0; o >>= 1) h2 += __shfl_xor_sync(0xffffffffu, h2, o);
    if (lane == 0) redbuf[wid] = h2;
    __syncthreads();
    if (tid == 0) {
        float s = 0.f;
#pragma unroll
        for (int w = 0; w < 8; w++) s += redbuf[w];
        atomicAdd(&g_h2sum, s);
    }

    // ---- last-CTA finalize: square-sum G, write scalar, reset state ----
    __threadfence();
    if (tid == 0) s_ticket = atomicAdd(&g_count, 1u);
    __syncthreads();
    if (s_ticket != NCTAS - 1) return;

    double s = 0.0;
    for (int i = tid; i < KCL * DDIM; i += 256) {
        float v = __ldcg(&g_partial[i]);
        s += (double)v * (double)v;
        g_partial[i] = 0.f;              // re-zero for next graph replay
    }
#pragma unroll
    for (int o = 16; o > 0; o >>= 1) s += __shfl_xor_sync(0xffffffffu, s, o);
    if (lane == 0) sb[wid] = s;
    __syncthreads();
    if (tid == 0) {
        double tot = 0.0;
#pragma unroll
        for (int w = 0; w < 8; w++) tot += sb[w];
        float h2tot = __ldcg(&g_h2sum);
        out[0] = (float)((double)h2tot - tot);
        g_h2sum = 0.f;
        g_count = 0u;
    }
}

extern "C" void kernel_launch(void* const* d_in, const int* in_sizes, int n_in,
                              void* d_out, int out_size) {
    const float* Hp;
    const float* Fp;
    if (in_sizes[0] == NTOT * DDIM) {
        Hp = (const float*)d_in[0];
        Fp = (const float*)d_in[1];
    } else {
        Hp = (const float*)d_in[1];
        Fp = (const float*)d_in[0];
    }

    dim3 grid(DTILES, NCHUNKS);
    k_fused<<<grid, 256>>>(Hp, Fp, (float*)d_out);
}